// round 1
// baseline (speedup 1.0000x reference)
#include <cuda_runtime.h>

// ============================================================================
// AttentionLayer: two attention-pool modules over X_in/X_out + linear + ELU.
//
// Math notes:
//   scores_j = a_w.X[0] + X_j.b_w ; alpha = exp(scores)
//   sum_output = (alpha @ X) / sum(alpha)
//   The constant a_w.X[0] cancels in the normalized ratio -> a_alpha unused.
//
// Strategy: single fused pass over X (read once, 410MB total), block-local
// accumulation, atomic combine into __device__ globals. 5 kernels, all
// graph-capturable, no allocations.
// ============================================================================

#define DD 1024
#define CHUNKS 224
#define TPB 256

__device__ __align__(16) float g_bw[2][DD];     // b_alpha^T @ W_alpha per module
__device__ __align__(16) float g_V[2][DD];      // sum_j w_j * X_j
__device__ float g_S[2];                        // sum_j w_j
__device__ __align__(16) float g_attn[2 * DD];  // concat(res_in, res_out)

// ----------------------------------------------------------------------------
// K0: zero all accumulators (re-run every graph replay => deterministic)
// ----------------------------------------------------------------------------
__global__ void k_zero() {
    int t = blockIdx.x * blockDim.x + threadIdx.x;
    if (t < DD) {
        g_bw[0][t] = 0.f; g_bw[1][t] = 0.f;
        g_V[0][t]  = 0.f; g_V[1][t]  = 0.f;
        g_attn[t]  = 0.f; g_attn[DD + t] = 0.f;
    }
    if (t < 2) g_S[t] = 0.f;
}

// ----------------------------------------------------------------------------
// K1: b_w[d] = sum_k b_alpha[k] * W_alpha[k][d]   (k-split + atomic combine)
// grid: (16 k-chunks, 2 modules), 256 threads; each thread owns 4 d-columns
// ----------------------------------------------------------------------------
__global__ void k_bw(const float* __restrict__ Wa_in, const float* __restrict__ ba_in,
                     const float* __restrict__ Wa_out, const float* __restrict__ ba_out) {
    int m = blockIdx.y;
    const float* W = m ? Wa_out : Wa_in;
    const float* b = m ? ba_out : ba_in;
    int t = threadIdx.x;
    int k0 = blockIdx.x * 64;
    float acc[4] = {0.f, 0.f, 0.f, 0.f};
    for (int kk = 0; kk < 64; kk++) {
        int k = k0 + kk;
        float bv = b[k];
        const float* row = W + (size_t)k * DD;
#pragma unroll
        for (int i = 0; i < 4; i++)
            acc[i] += bv * row[t + i * TPB];
    }
#pragma unroll
    for (int i = 0; i < 4; i++)
        atomicAdd(&g_bw[m][t + i * TPB], acc[i]);
}

// ----------------------------------------------------------------------------
// K2: fused main pass. Each block handles a contiguous chunk of rows,
// 4 rows per iteration. Per iteration:
//   - (prefetched) 4 rows held as one float4 per thread (256 thr * 16B = 4KB row)
//   - per-row dot with b_w: warp shuffle reduce + cross-warp smem reduce
//   - w_r = exp(s_r) broadcast; acc += w_r * x_r from registers (no re-read)
// Block partials -> atomicAdd into g_V/g_S.
// ----------------------------------------------------------------------------
__global__ void __launch_bounds__(TPB) k_main(const float* __restrict__ Xin,
                                              const float* __restrict__ Xout, int N) {
    int m = blockIdx.y;
    const float* X = m ? Xout : Xin;
    int t = threadIdx.x, lane = t & 31, wid = t >> 5;
    __shared__ float s_warp[4][8];
    __shared__ float s_w[4];

    float4 bw4 = ((const float4*)g_bw[m])[t];

    int rb = ((N + CHUNKS - 1) / CHUNKS + 3) & ~3;  // rows per block, mult of 4
    int row0 = blockIdx.x * rb;
    int iters = rb >> 2;

    float4 acc = make_float4(0.f, 0.f, 0.f, 0.f);
    float blockS = 0.f;

    float4 x[4];
#pragma unroll
    for (int r = 0; r < 4; r++) {
        int row = row0 + r;
        x[r] = (row < N) ? ((const float4*)(X + (size_t)row * DD))[t]
                         : make_float4(0.f, 0.f, 0.f, 0.f);
    }

    for (int it = 0; it < iters; it++) {
        float4 xn[4];
        bool has_next = (it + 1 < iters);
        int nrow0 = row0 + (it + 1) * 4;
        if (has_next) {
#pragma unroll
            for (int r = 0; r < 4; r++) {
                int row = nrow0 + r;
                xn[r] = (row < N) ? ((const float4*)(X + (size_t)row * DD))[t]
                                  : make_float4(0.f, 0.f, 0.f, 0.f);
            }
        }

        float p[4];
#pragma unroll
        for (int r = 0; r < 4; r++) {
            p[r] = x[r].x * bw4.x + x[r].y * bw4.y + x[r].z * bw4.z + x[r].w * bw4.w;
#pragma unroll
            for (int off = 16; off; off >>= 1)
                p[r] += __shfl_xor_sync(0xffffffffu, p[r], off);
        }
        if (lane == 0) {
#pragma unroll
            for (int r = 0; r < 4; r++) s_warp[r][wid] = p[r];
        }
        __syncthreads();
        if (t < 4) {
            float s = 0.f;
#pragma unroll
            for (int w = 0; w < 8; w++) s += s_warp[t][w];
            int row = row0 + it * 4 + t;
            s_w[t] = (row < N) ? __expf(s) : 0.f;
        }
        __syncthreads();
        float w0 = s_w[0], w1 = s_w[1], w2 = s_w[2], w3 = s_w[3];

        acc.x += w0 * x[0].x + w1 * x[1].x + w2 * x[2].x + w3 * x[3].x;
        acc.y += w0 * x[0].y + w1 * x[1].y + w2 * x[2].y + w3 * x[3].y;
        acc.z += w0 * x[0].z + w1 * x[1].z + w2 * x[2].z + w3 * x[3].z;
        acc.w += w0 * x[0].w + w1 * x[1].w + w2 * x[2].w + w3 * x[3].w;
        if (t == 0) blockS += w0 + w1 + w2 + w3;

        if (has_next) {
#pragma unroll
            for (int r = 0; r < 4; r++) x[r] = xn[r];
        }
    }

    float* Vm = g_V[m];
    atomicAdd(&Vm[t * 4 + 0], acc.x);
    atomicAdd(&Vm[t * 4 + 1], acc.y);
    atomicAdd(&Vm[t * 4 + 2], acc.z);
    atomicAdd(&Vm[t * 4 + 3], acc.w);
    if (t == 0) atomicAdd(&g_S[m], blockS);
}

// ----------------------------------------------------------------------------
// K3: res[m][d] = sum_k (V[m][k]/S[m]) * W_sum[k][d] -> g_attn[m*D + d]
// same k-split structure as K1
// ----------------------------------------------------------------------------
__global__ void k_res(const float* __restrict__ Ws_in, const float* __restrict__ Ws_out) {
    int m = blockIdx.y;
    const float* W = m ? Ws_out : Ws_in;
    float invS = 1.f / g_S[m];
    int t = threadIdx.x;
    int k0 = blockIdx.x * 64;
    float acc[4] = {0.f, 0.f, 0.f, 0.f};
    for (int kk = 0; kk < 64; kk++) {
        int k = k0 + kk;
        float coef = g_V[m][k] * invS;
        const float* row = W + (size_t)k * DD;
#pragma unroll
        for (int i = 0; i < 4; i++)
            acc[i] += coef * row[t + i * TPB];
    }
#pragma unroll
    for (int i = 0; i < 4; i++)
        atomicAdd(&g_attn[m * DD + t + i * TPB], acc[i]);
}

// ----------------------------------------------------------------------------
// K4: out[i] = elu( lin_W[i,:] . attn + lin_b[i] )   (lin_W is [D, 2D] row-major)
// warp per output row; 8 outputs per block; 128 blocks
// ----------------------------------------------------------------------------
__global__ void k_out(const float* __restrict__ linW, const float* __restrict__ linb,
                      float* __restrict__ out) {
    int wid = threadIdx.x >> 5, lane = threadIdx.x & 31;
    int i = blockIdx.x * 8 + wid;
    const float4* row = (const float4*)(linW + (size_t)i * 2 * DD);  // 512 float4
    const float4* attn4 = (const float4*)g_attn;
    float s = 0.f;
#pragma unroll
    for (int it = 0; it < 16; it++) {
        float4 a = attn4[lane + it * 32];
        float4 w = row[lane + it * 32];
        s += a.x * w.x + a.y * w.y + a.z * w.z + a.w * w.w;
    }
#pragma unroll
    for (int off = 16; off; off >>= 1) s += __shfl_xor_sync(0xffffffffu, s, off);
    if (lane == 0) {
        float v = s + linb[i];
        out[i] = v > 0.f ? v : expm1f(v);
    }
}

// ----------------------------------------------------------------------------
// Launch
// ----------------------------------------------------------------------------
extern "C" void kernel_launch(void* const* d_in, const int* in_sizes, int n_in,
                              void* d_out, int out_size) {
    const float* X_in   = (const float*)d_in[0];
    const float* X_out  = (const float*)d_in[1];
    const float* Wa_in  = (const float*)d_in[2];
    // d_in[3] = a_alpha_in  (mathematically cancels; unused)
    const float* ba_in  = (const float*)d_in[4];
    const float* Ws_in  = (const float*)d_in[5];
    const float* Wa_out = (const float*)d_in[6];
    // d_in[7] = a_alpha_out (unused)
    const float* ba_out = (const float*)d_in[8];
    const float* Ws_out = (const float*)d_in[9];
    const float* linW   = (const float*)d_in[10];
    const float* linb   = (const float*)d_in[11];
    float* out = (float*)d_out;
    int N = in_sizes[0] / DD;

    k_zero<<<4, TPB>>>();
    k_bw  <<<dim3(16, 2), TPB>>>(Wa_in, ba_in, Wa_out, ba_out);
    k_main<<<dim3(CHUNKS, 2), TPB>>>(X_in, X_out, N);
    k_res <<<dim3(16, 2), TPB>>>(Ws_in, Ws_out);
    k_out <<<128, TPB>>>(linW, linb, out);
}

// round 14
// speedup vs baseline: 1.4880x; 1.4880x over previous
#include <cuda_runtime.h>

// ============================================================================
// AttentionLayer: two attention-pool modules over X_in/X_out + linear + ELU.
//
// Math: scores_j = a_w.X[0] + X_j.b_w; the constant a_w.X[0] cancels in
// (alpha@X)/sum(alpha) -> a_alpha is dead. Single fused streaming pass over X.
//
// R2 design (unmeasured: GPU timeouts R2-R13; resubmitting unchanged):
//  - k_bw/k_res: 128 blocks, float4/thread, fully unrolled (MLP=16).
//    R1 ncu showed k_res at 419GB/s / occ 12% -> ~40us combined for 16MB.
//  - k_main: grid (148,2), 2 blocks/SM = single balanced wave; 8 rows/iter,
//    register double-buffer prefetch, ONE barrier per iter (double-buffered
//    smem partials + redundant per-thread exp).
// ============================================================================

#define DD 1024
#define CHUNKS 148
#define RPI 8
#define TPB 256

__device__ __align__(16) float g_bw[2][DD];
__device__ __align__(16) float g_V[2][DD];
__device__ float g_S[2];
__device__ __align__(16) float g_attn[2 * DD];

// ----------------------------------------------------------------------------
// K0: zero accumulators (graph replays must be deterministic)
// ----------------------------------------------------------------------------
__global__ void k_zero() {
    int t = blockIdx.x * blockDim.x + threadIdx.x;
    if (t < DD) {
        g_bw[0][t] = 0.f; g_bw[1][t] = 0.f;
        g_V[0][t]  = 0.f; g_V[1][t]  = 0.f;
        g_attn[t]  = 0.f; g_attn[DD + t] = 0.f;
    }
    if (t < 2) g_S[t] = 0.f;
}

// ----------------------------------------------------------------------------
// K1: b_w[d] = sum_k b_alpha[k] * W_alpha[k][d]
// grid (64 k-chunks, 2 modules) x 256 thr; 16 rows/block, float4/thread
// ----------------------------------------------------------------------------
__global__ void __launch_bounds__(TPB) k_bw(const float* __restrict__ Wa_in,
                                            const float* __restrict__ ba_in,
                                            const float* __restrict__ Wa_out,
                                            const float* __restrict__ ba_out) {
    int m = blockIdx.y;
    const float* W = m ? Wa_out : Wa_in;
    const float* b = m ? ba_out : ba_in;
    int t = threadIdx.x;
    int k0 = blockIdx.x * 16;
    float ax = 0.f, ay = 0.f, az = 0.f, aw = 0.f;
#pragma unroll
    for (int kk = 0; kk < 16; kk++) {
        float bv = b[k0 + kk];
        float4 r = ((const float4*)(W + (size_t)(k0 + kk) * DD))[t];
        ax += bv * r.x; ay += bv * r.y; az += bv * r.z; aw += bv * r.w;
    }
    float* dst = &g_bw[m][t * 4];
    atomicAdd(dst + 0, ax); atomicAdd(dst + 1, ay);
    atomicAdd(dst + 2, az); atomicAdd(dst + 3, aw);
}

// ----------------------------------------------------------------------------
// K2: fused main pass. 8 rows/iter, register double-buffer, 1 barrier/iter.
// ----------------------------------------------------------------------------
__global__ void __launch_bounds__(TPB, 2) k_main(const float* __restrict__ Xin,
                                                 const float* __restrict__ Xout,
                                                 int N) {
    int m = blockIdx.y;
    const float* X = m ? Xout : Xin;
    int t = threadIdx.x, lane = t & 31, wid = t >> 5;
    __shared__ float s_warp[2][RPI][8];

    float4 bw4 = ((const float4*)g_bw[m])[t];

    int rb = ((N + CHUNKS - 1) / CHUNKS + RPI - 1) & ~(RPI - 1);
    int row0 = blockIdx.x * rb;
    int iters = rb / RPI;

    float4 acc = make_float4(0.f, 0.f, 0.f, 0.f);
    float blockS = 0.f;

    float4 x[RPI];
#pragma unroll
    for (int r = 0; r < RPI; r++) {
        int row = row0 + r;
        x[r] = (row < N) ? ((const float4*)(X + (size_t)row * DD))[t]
                         : make_float4(0.f, 0.f, 0.f, 0.f);
    }

    int buf = 0;
    for (int it = 0; it < iters; it++) {
        float4 xn[RPI];
        bool has_next = (it + 1 < iters);
        int nrow0 = row0 + (it + 1) * RPI;
        if (has_next) {
#pragma unroll
            for (int r = 0; r < RPI; r++) {
                int row = nrow0 + r;
                xn[r] = (row < N) ? ((const float4*)(X + (size_t)row * DD))[t]
                                  : make_float4(0.f, 0.f, 0.f, 0.f);
            }
        }

        // per-row dot with b_w: warp shuffle reduce
        float p[RPI];
#pragma unroll
        for (int r = 0; r < RPI; r++) {
            p[r] = x[r].x * bw4.x + x[r].y * bw4.y + x[r].z * bw4.z + x[r].w * bw4.w;
#pragma unroll
            for (int off = 16; off; off >>= 1)
                p[r] += __shfl_xor_sync(0xffffffffu, p[r], off);
        }
        if (lane == 0) {
#pragma unroll
            for (int r = 0; r < RPI; r++) s_warp[buf][r][wid] = p[r];
        }
        __syncthreads();  // only barrier in the loop (double-buffered smem)

        int base = row0 + it * RPI;
        float w[RPI];
#pragma unroll
        for (int r = 0; r < RPI; r++) {
            float s = 0.f;
#pragma unroll
            for (int ww = 0; ww < 8; ww++) s += s_warp[buf][r][ww];
            w[r] = (base + r < N) ? __expf(s) : 0.f;
        }

#pragma unroll
        for (int r = 0; r < RPI; r++) {
            acc.x += w[r] * x[r].x;
            acc.y += w[r] * x[r].y;
            acc.z += w[r] * x[r].z;
            acc.w += w[r] * x[r].w;
        }
        if (t == 0) {
            float sw = 0.f;
#pragma unroll
            for (int r = 0; r < RPI; r++) sw += w[r];
            blockS += sw;
        }

        if (has_next) {
#pragma unroll
            for (int r = 0; r < RPI; r++) x[r] = xn[r];
        }
        buf ^= 1;
    }

    float* Vm = g_V[m];
    atomicAdd(&Vm[t * 4 + 0], acc.x);
    atomicAdd(&Vm[t * 4 + 1], acc.y);
    atomicAdd(&Vm[t * 4 + 2], acc.z);
    atomicAdd(&Vm[t * 4 + 3], acc.w);
    if (t == 0) atomicAdd(&g_S[m], blockS);
}

// ----------------------------------------------------------------------------
// K3: res[m][d] = sum_k (V[m][k]/S[m]) * W_sum[k][d]
// same structure as K1: grid (64,2), 16 rows/block, float4/thread
// ----------------------------------------------------------------------------
__global__ void __launch_bounds__(TPB) k_res(const float* __restrict__ Ws_in,
                                             const float* __restrict__ Ws_out) {
    int m = blockIdx.y;
    const float* W = m ? Ws_out : Ws_in;
    float invS = 1.f / g_S[m];
    int t = threadIdx.x;
    int k0 = blockIdx.x * 16;
    float ax = 0.f, ay = 0.f, az = 0.f, aw = 0.f;
#pragma unroll
    for (int kk = 0; kk < 16; kk++) {
        float coef = g_V[m][k0 + kk] * invS;
        float4 r = ((const float4*)(W + (size_t)(k0 + kk) * DD))[t];
        ax += coef * r.x; ay += coef * r.y; az += coef * r.z; aw += coef * r.w;
    }
    float* dst = &g_attn[m * DD + t * 4];
    atomicAdd(dst + 0, ax); atomicAdd(dst + 1, ay);
    atomicAdd(dst + 2, az); atomicAdd(dst + 3, aw);
}

// ----------------------------------------------------------------------------
// K4: out[i] = elu( lin_W[i,:] . attn + lin_b[i] ), lin_W row-major [D, 2D]
// ----------------------------------------------------------------------------
__global__ void __launch_bounds__(TPB) k_out(const float* __restrict__ linW,
                                             const float* __restrict__ linb,
                                             float* __restrict__ out) {
    int wid = threadIdx.x >> 5, lane = threadIdx.x & 31;
    int i = blockIdx.x * 8 + wid;
    const float4* row = (const float4*)(linW + (size_t)i * 2 * DD);
    const float4* attn4 = (const float4*)g_attn;
    float s = 0.f;
#pragma unroll
    for (int it = 0; it < 16; it++) {
        float4 a = attn4[lane + it * 32];
        float4 w = row[lane + it * 32];
        s += a.x * w.x + a.y * w.y + a.z * w.z + a.w * w.w;
    }
#pragma unroll
    for (int off = 16; off; off >>= 1) s += __shfl_xor_sync(0xffffffffu, s, off);
    if (lane == 0) {
        float v = s + linb[i];
        out[i] = v > 0.f ? v : expm1f(v);
    }
}

// ----------------------------------------------------------------------------
// Launch
// ----------------------------------------------------------------------------
extern "C" void kernel_launch(void* const* d_in, const int* in_sizes, int n_in,
                              void* d_out, int out_size) {
    const float* X_in   = (const float*)d_in[0];
    const float* X_out  = (const float*)d_in[1];
    const float* Wa_in  = (const float*)d_in[2];
    // d_in[3] = a_alpha_in  (cancels; unused)
    const float* ba_in  = (const float*)d_in[4];
    const float* Ws_in  = (const float*)d_in[5];
    const float* Wa_out = (const float*)d_in[6];
    // d_in[7] = a_alpha_out (unused)
    const float* ba_out = (const float*)d_in[8];
    const float* Ws_out = (const float*)d_in[9];
    const float* linW   = (const float*)d_in[10];
    const float* linb   = (const float*)d_in[11];
    float* out = (float*)d_out;
    int N = in_sizes[0] / DD;

    k_zero<<<4, TPB>>>();
    k_bw  <<<dim3(64, 2), TPB>>>(Wa_in, ba_in, Wa_out, ba_out);
    k_main<<<dim3(CHUNKS, 2), TPB>>>(X_in, X_out, N);
    k_res <<<dim3(64, 2), TPB>>>(Ws_in, Ws_out);
    k_out <<<128, TPB>>>(linW, linb, out);
}